// round 15
// baseline (speedup 1.0000x reference)
#include <cuda_runtime.h>
#include <cuda_bf16.h>
#include <cstdint>
#include <cstddef>

#define Bz 8192
#define Nz 64
#define Dz 256
#define Hz 8
#define HHz 32
#define KTOT (Hz*Dz) /* 2048 */

// ---------------- scratch (static device globals; no allocations) ----------
__device__ float g_wv[16*Dz];                       // combined score vectors f32
__device__ uint4 g_wfH[512];                        // score B-fragments hi [wn][kk2][lane]
__device__ uint4 g_wfL[512];                        // score B-fragments lo
__device__ __nv_bfloat16 g_WTh[Dz*Dz];              // W   split hi [r][d] (r=h*32+j)
__device__ __nv_bfloat16 g_WTl[Dz*Dz];
__device__ __nv_bfloat16 g_WOh[Dz*Dz];              // W_out split hi [e][k]
__device__ __nv_bfloat16 g_WOl[Dz*Dz];
__device__ __nv_bfloat16 g_Gh[(size_t)Bz*KTOT];     // 32MB G hi [b][k]
__device__ __nv_bfloat16 g_Gl[(size_t)Bz*KTOT];     // 32MB G lo [b][k]
__device__ __nv_bfloat16 g_Fh[(size_t)Bz*Dz];       // 4MB  F hi [b][k'] (k'=h*32+j)
__device__ __nv_bfloat16 g_Fl[(size_t)Bz*Dz];

// ---------------- helpers ---------------------------------------------------
__device__ __forceinline__ uint32_t smem_u32(const void* p){
    uint32_t a;
    asm("{ .reg .u64 t; cvta.to.shared.u64 t, %1; cvt.u32.u64 %0, t; }" : "=r"(a) : "l"(p));
    return a;
}
__device__ __forceinline__ void ldm_x4(uint32_t &r0, uint32_t &r1, uint32_t &r2,
                                       uint32_t &r3, uint32_t addr){
    asm volatile("ldmatrix.sync.aligned.m8n8.x4.shared.b16 {%0,%1,%2,%3}, [%4];"
                 : "=r"(r0), "=r"(r1), "=r"(r2), "=r"(r3) : "r"(addr));
}
__device__ __forceinline__ void ldm_x4_t(uint32_t &r0, uint32_t &r1, uint32_t &r2,
                                         uint32_t &r3, uint32_t addr){
    asm volatile("ldmatrix.sync.aligned.m8n8.x4.trans.shared.b16 {%0,%1,%2,%3}, [%4];"
                 : "=r"(r0), "=r"(r1), "=r"(r2), "=r"(r3) : "r"(addr));
}
__device__ __forceinline__ void mma_bf16(float* c, const uint32_t* a,
                                         uint32_t b0, uint32_t b1){
    asm volatile(
        "mma.sync.aligned.m16n8k16.row.col.f32.bf16.bf16.f32 "
        "{%0,%1,%2,%3}, {%4,%5,%6,%7}, {%8,%9}, {%0,%1,%2,%3};"
        : "+f"(c[0]), "+f"(c[1]), "+f"(c[2]), "+f"(c[3])
        : "r"(a[0]), "r"(a[1]), "r"(a[2]), "r"(a[3]), "r"(b0), "r"(b1));
}
__device__ __forceinline__ void cpasync16(uint32_t dst, const void* src){
    asm volatile("cp.async.cg.shared.global [%0], [%1], 16;" :: "r"(dst), "l"(src) : "memory");
}
#define CP_COMMIT() asm volatile("cp.async.commit_group;" ::: "memory")
#define CP_WAIT(n)  asm volatile("cp.async.wait_group %0;" :: "n"(n) : "memory")

__device__ __forceinline__ uint32_t bf16pack(float a, float b){
    unsigned short u0 = __bfloat16_as_ushort(__float2bfloat16(a));
    unsigned short u1 = __bfloat16_as_ushort(__float2bfloat16(b));
    return (uint32_t)u0 | ((uint32_t)u1 << 16);
}
// pack two f32 -> bf16x2 in ONE cvt (first arg -> LOWER half). rn rounding.
__device__ __forceinline__ uint32_t cvt2(float lo, float hi){
    uint32_t r;
    asm("cvt.rn.bf16x2.f32 %0, %2, %1;" : "=r"(r) : "f"(lo), "f"(hi));
    return r;
}

// ---------------- K1a: wv[j][d] (parallel over 16 blocks) ------------------
__global__ __launch_bounds__(256)
void prep_wv_kernel(const float* __restrict__ W,
                    const float* __restrict__ cur_a,
                    const float* __restrict__ nb_a){
    int j = blockIdx.x;              // 0..15
    int d = threadIdx.x;
    int h = j & 7;
    const float* av = (j < 8) ? (nb_a + h*HHz) : (cur_a + h*HHz);
    float s = 0.f;
    #pragma unroll
    for (int k = 0; k < HHz; k++)
        s += av[k] * W[(h*HHz + k)*Dz + d];
    g_wv[j*Dz + d] = s;
}

// ---------------- K1b: wv -> mma B-fragment layout -------------------------
__global__ __launch_bounds__(512)
void prep_frag_kernel(){
    int t = threadIdx.x;
    int wn = t >> 8, kk2 = (t >> 5) & 7, l = t & 31;
    int j = wn*8 + (l >> 2);
    int k0 = (l & 3)*2;
    const float* row = g_wv + j*Dz + kk2*32;
    uint32_t hx[4], lx[4];
    #pragma unroll
    for (int s = 0; s < 2; s++){
        #pragma unroll
        for (int half = 0; half < 2; half++){
            float a = row[s*16 + half*8 + k0];
            float b = row[s*16 + half*8 + k0 + 1];
            float ah = __bfloat162float(__float2bfloat16(a));
            float bh = __bfloat162float(__float2bfloat16(b));
            hx[s*2 + half] = bf16pack(a, b);
            lx[s*2 + half] = bf16pack(a - ah, b - bh);
        }
    }
    g_wfH[t] = make_uint4(hx[0], hx[1], hx[2], hx[3]);
    g_wfL[t] = make_uint4(lx[0], lx[1], lx[2], lx[3]);
}

// ---------------- K1c: merged elementwise bf16 hi/lo splits ----------------
__global__ __launch_bounds__(512)
void prep_split_kernel(const float* __restrict__ W,
                       const float* __restrict__ W_out){
    int idx = blockIdx.x*512 + threadIdx.x;     // 0..65535
    float w = W[idx];
    __nv_bfloat16 hb = __float2bfloat16(w);
    g_WTh[idx] = hb;
    g_WTl[idx] = __float2bfloat16(w - __bfloat162float(hb));
    float wo = W_out[idx];
    __nv_bfloat16 ho = __float2bfloat16(wo);
    g_WOh[idx] = ho;
    g_WOl[idx] = __float2bfloat16(wo - __bfloat162float(ho));
}

// ---------------- K2: tensor-core fused attention --------------------------
// smem byte offsets (74.0 KB total -> 3 blocks/SM)
#define O_XH 0                  /* 32768 */
#define O_XL 32768              /* 32768 */
#define O_SS 65536              /* f32 [64][17] = 4352; later reused as G staging (8448B) */
#define O_AH 69888              /* 2048 */
#define O_AL 71936              /* 2048 */
#define SMEM_ATTN 73984

__global__ __launch_bounds__(256, 3)
void attn_kernel(const float* __restrict__ inter,
                 const int*   __restrict__ lengths,
                 float*       __restrict__ out){
    extern __shared__ char smem[];
    uint32_t sb = smem_u32(smem);
    float* sS = (float*)(smem + O_SS);

    int b = blockIdx.x;
    int t = threadIdx.x;
    int wid = t >> 5, l = t & 31;
    int l7 = l & 7;
    int lr8 = ((l >> 3) & 1)*8 + l7;
    int jj4 = (l >> 4) & 1;

    // ---- load X with 8-deep register prefetch, convert, store ----
    {
        const float4* src = (const float4*)(inter + (size_t)b*Nz*Dz);
        float4 buf[8];
        #pragma unroll
        for (int i = 0; i < 8; i++) buf[i] = src[t + 256*i];

        #pragma unroll
        for (int i = 0; i < 16; i++){
            float4 v = buf[i & 7];
            if (i < 8) buf[i & 7] = src[t + 256*(i + 8)];
            int g  = t + 256*i;
            int n  = g >> 6, c4 = g & 63;
            uint32_t off = (uint32_t)(n*512 + (((c4 >> 1) ^ (n & 7)) << 4) + (c4 & 1)*8);
            uint32_t h01 = cvt2(v.x, v.y);
            uint32_t h23 = cvt2(v.z, v.w);
            float fa = __uint_as_float(h01 << 16);
            float fb = __uint_as_float(h01 & 0xffff0000u);
            float fc = __uint_as_float(h23 << 16);
            float fd = __uint_as_float(h23 & 0xffff0000u);
            uint32_t l01 = cvt2(v.x - fa, v.y - fb);
            uint32_t l23 = cvt2(v.z - fc, v.w - fd);
            *(uint2*)(smem + O_XH + off) = make_uint2(h01, h23);
            *(uint2*)(smem + O_XL + off) = make_uint2(l01, l23);
            if (i == 0 && n == 0)
                *(float4*)(out + (size_t)Bz*Dz + (size_t)b*Dz + c4*4) = v;
        }
    }
    __syncthreads();

    // ---- score phase: S(64x16) = X . W^T; 2 independent acc chains --------
    {
        int wm = wid >> 1;
        int wn = wid & 1;
        uint32_t aH = sb + O_XH + (uint32_t)((wm*16 + lr8)*512);
        uint32_t aL = sb + O_XL + (uint32_t)((wm*16 + lr8)*512);
        const uint4* pH = g_wfH + wn*256 + l;
        const uint4* pL = g_wfL + wn*256 + l;

        float c0[4] = {0.f, 0.f, 0.f, 0.f};
        float c1[4] = {0.f, 0.f, 0.f, 0.f};
        #pragma unroll
        for (int kk2 = 0; kk2 < 8; kk2++){
            float* c = (kk2 & 1) ? c1 : c0;
            uint4 bh = pH[kk2*32];
            uint4 bl = pL[kk2*32];
            #pragma unroll
            for (int s = 0; s < 2; s++){
                int kk = kk2*2 + s;
                uint32_t ao = (((uint32_t)(kk*2 + jj4) ^ l7) << 4);
                uint32_t ah[4], al[4];
                ldm_x4(ah[0], ah[1], ah[2], ah[3], aH + ao);
                ldm_x4(al[0], al[1], al[2], al[3], aL + ao);
                uint32_t b0h = s ? bh.z : bh.x, b1h = s ? bh.w : bh.y;
                uint32_t b0l = s ? bl.z : bl.x, b1l = s ? bl.w : bl.y;
                mma_bf16(c, ah, b0h, b1h);
                mma_bf16(c, ah, b0l, b1l);
                mma_bf16(c, al, b0h, b1h);
            }
        }
        int r0 = wm*16 + (l >> 2);
        int jc = wn*8 + (l & 3)*2;
        sS[r0*17 + jc]           = c0[0] + c1[0];
        sS[r0*17 + jc + 1]       = c0[1] + c1[1];
        sS[(r0 + 8)*17 + jc]     = c0[2] + c1[2];
        sS[(r0 + 8)*17 + jc + 1] = c0[3] + c1[3];
    }
    __syncthreads();

    // ---- softmax per head (warp w = head h), write attn bf16 hi/lo ----
    {
        ((uint32_t*)(smem + O_AH))[256 + t] = 0u;
        ((uint32_t*)(smem + O_AL))[256 + t] = 0u;

        int h = wid;
        float cur = sS[8 + h];
        int len = lengths[b]; if (len < 1) len = 1;

        float v0 = cur + sS[l*17 + h];
        float v1 = cur + sS[(l + 32)*17 + h];
        v0 = v0 > 0.f ? v0 : 0.01f*v0;
        v1 = v1 > 0.f ? v1 : 0.01f*v1;
        bool m0 = (l < len), m1 = ((l + 32) < len);
        float y0 = m0 ? v0 : -3.0e38f;
        float y1 = m1 ? v1 : -3.0e38f;
        float mx = fmaxf(y0, y1);
        #pragma unroll
        for (int off = 16; off > 0; off >>= 1)
            mx = fmaxf(mx, __shfl_xor_sync(0xffffffffu, mx, off));
        float e0 = m0 ? __expf(v0 - mx) : 0.f;
        float e1 = m1 ? __expf(v1 - mx) : 0.f;
        float s = e0 + e1;
        #pragma unroll
        for (int off = 16; off > 0; off >>= 1)
            s += __shfl_xor_sync(0xffffffffu, s, off);
        float inv = 1.f / s;
        float a0 = e0 * inv, a1 = e1 * inv;

        int hs = h & 7;
        #pragma unroll
        for (int q = 0; q < 2; q++){
            int n = l + 32*q;
            float a = q ? a1 : a0;
            __nv_bfloat16 hb = __float2bfloat16(a);
            float lo = a - __bfloat162float(hb);
            uint32_t off = (uint32_t)(h*128 + (((n >> 3) ^ hs) << 4) + (n & 7)*2);
            *(__nv_bfloat16*)(smem + O_AH + off) = hb;
            *(__nv_bfloat16*)(smem + O_AL + off) = __float2bfloat16(lo);
        }
    }
    __syncthreads();

    // ---- G phase: G(16x256) = attn^T(16x64) . X(64x256), warp = 32 d ----
    float g[4][4];
    {
        #pragma unroll
        for (int i = 0; i < 4; i++)
            #pragma unroll
            for (int j = 0; j < 4; j++) g[i][j] = 0.f;

        uint32_t aHb = sb + O_AH + (uint32_t)(lr8*128);
        uint32_t aLb = sb + O_AL + (uint32_t)(lr8*128);

        #pragma unroll
        for (int ks = 0; ks < 4; ks++){
            uint32_t ao = (((uint32_t)(ks*2 + jj4) ^ l7) << 4);
            uint32_t ah[4], al[4];
            ldm_x4(ah[0], ah[1], ah[2], ah[3], aHb + ao);
            ldm_x4(al[0], al[1], al[2], al[3], aLb + ao);

            uint32_t rowb = (uint32_t)((ks*16 + lr8)*512);
            #pragma unroll
            for (int pair = 0; pair < 2; pair++){
                uint32_t ch = (uint32_t)(wid*4 + pair*2 + jj4);
                uint32_t xo = rowb + ((ch ^ l7) << 4);
                uint32_t xh[4], xl[4];
                ldm_x4_t(xh[0], xh[1], xh[2], xh[3], sb + O_XH + xo);
                ldm_x4_t(xl[0], xl[1], xl[2], xl[3], sb + O_XL + xo);
                mma_bf16(g[pair*2 + 0], ah, xh[0], xh[1]);
                mma_bf16(g[pair*2 + 0], ah, xl[0], xl[1]);
                mma_bf16(g[pair*2 + 0], al, xh[0], xh[1]);
                mma_bf16(g[pair*2 + 1], ah, xh[2], xh[3]);
                mma_bf16(g[pair*2 + 1], ah, xl[2], xl[3]);
                mma_bf16(g[pair*2 + 1], al, xh[2], xh[3]);
            }
        }
    }
    __syncthreads();   // all G-phase smem reads done; staging may overwrite

    // ---- stage G fragments (conflict-free), then coalesced writeout ----
    {
        uint32_t* sG32 = (uint32_t*)(smem + O_SS);   // hi [8][132], lo at +1056
        int h = l >> 2;
        #pragma unroll
        for (int i = 0; i < 4; i++){
            uint32_t h01 = cvt2(g[i][0], g[i][1]);
            float fa = __uint_as_float(h01 << 16);
            float fb = __uint_as_float(h01 & 0xffff0000u);
            uint32_t l01 = cvt2(g[i][0] - fa, g[i][1] - fb);
            int idx = h*132 + wid*16 + i*4 + (l & 3);
            sG32[idx]        = h01;
            sG32[1056 + idx] = l01;
        }
    }
    __syncthreads();
    {
        int row = t >> 5, c = t & 31;
        uint32_t* sG32 = (uint32_t*)(smem + O_SS);
        uint4 vh = *(uint4*)(sG32 + row*132 + c*4);
        uint4 vl = *(uint4*)(sG32 + 1056 + row*132 + c*4);
        uint32_t* Gh = (uint32_t*)(g_Gh + (size_t)b*KTOT);
        uint32_t* Gl = (uint32_t*)(g_Gl + (size_t)b*KTOT);
        *(uint4*)(Gh + row*128 + c*4) = vh;
        *(uint4*)(Gl + row*128 + c*4) = vl;
    }
}

// ---------------- K3a: F[b, h*32+j] = sum_d G[b,(h,d)] W[h*32+j, d] --------
#define STGA 20480
#define SMEM_FA (2*STGA)

__global__ __launch_bounds__(256, 3)
void f_gemm_kernel(){
    extern __shared__ char smemA[];
    uint32_t sb = smem_u32(smemA);
    int t = threadIdx.x;
    int wid = t >> 5, l = t & 31;
    int wm = wid & 3, wn = wid >> 2;
    int row0 = blockIdx.x * 128;
    int h    = blockIdx.y;

    uint32_t dsw[5];
    const char* srcp[5];
    {
        const char* gAh = (const char*)g_Gh  + (size_t)row0*4096 + (size_t)h*512;
        const char* gAl = (const char*)g_Gl  + (size_t)row0*4096 + (size_t)h*512;
        const char* gBh = (const char*)g_WTh + (size_t)h*32*512;
        const char* gBl = (const char*)g_WTl + (size_t)h*32*512;
        #pragma unroll
        for (int i = 0; i < 5; i++){
            int q = t + 256*i;
            const char* base; uint32_t rb; int r; size_t rstride;
            if      (q < 512)  { base = gAh; rb = 0;     r = q;        rstride = 4096; }
            else if (q < 1024) { base = gAl; rb = 8192;  r = q - 512;  rstride = 4096; }
            else if (q < 1152) { base = gBh; rb = 16384; r = q - 1024; rstride = 512; }
            else               { base = gBl; rb = 18432; r = q - 1152; rstride = 512; }
            int row = r >> 2, jj = r & 3;
            int line = row >> 1;
            dsw[i]  = rb + (uint32_t)(line*128 + ((((row & 1)*4 + jj) ^ (line & 7))*16));
            srcp[i] = base + (size_t)row*rstride + (size_t)jj*16;
        }
    }

    uint32_t offA[2][2], offB[2];
    {
        int lr8 = ((l >> 3) & 1)*8 + (l & 7);
        int jj = l >> 4;
        #pragma unroll
        for (int mi = 0; mi < 2; mi++){
            int row = wm*32 + mi*16 + lr8;
            int line = row >> 1;
            #pragma unroll
            for (int ks = 0; ks < 2; ks++)
                offA[mi][ks] = (uint32_t)(line*128 + ((((row & 1)*4 + 2*ks + jj) ^ (line & 7))*16));
        }
        {
            int row = wn*16 + lr8;
            int line = row >> 1;
            #pragma unroll
            for (int ks = 0; ks < 2; ks++)
                offB[ks] = (uint32_t)(line*128 + ((((row & 1)*4 + 2*ks + jj) ^ (line & 7))*16));
        }
    }

    float acc[2][2][4];
    #pragma unroll
    for (int mi = 0; mi < 2; mi++)
        #pragma unroll
        for (int na = 0; na < 2; na++)
            #pragma unroll
            for (int i = 0; i < 4; i++) acc[mi][na][i] = 0.f;

    #pragma unroll
    for (int i = 0; i < 5; i++)
        cpasync16(sb + dsw[i], srcp[i]);
    CP_COMMIT();

    for (int c = 0; c < 8; c++){
        if (c + 1 < 8){
            uint32_t stg = sb + (uint32_t)((c + 1) & 1)*STGA;
            #pragma unroll
            for (int i = 0; i < 5; i++)
                cpasync16(stg + dsw[i], srcp[i] + (size_t)(c + 1)*64);
            CP_COMMIT();
            CP_WAIT(1);
        } else {
            CP_WAIT(0);
        }
        __syncthreads();

        uint32_t base = sb + (uint32_t)(c & 1)*STGA;
        uint32_t Ah = base, Al = base + 8192, Bh = base + 16384, Bl = base + 18432;
        #pragma unroll
        for (int ks = 0; ks < 2; ks++){
            uint32_t ah[2][4], al[2][4], bh[4], bl[4];
            #pragma unroll
            for (int mi = 0; mi < 2; mi++){
                ldm_x4(ah[mi][0], ah[mi][1], ah[mi][2], ah[mi][3], Ah + offA[mi][ks]);
                ldm_x4(al[mi][0], al[mi][1], al[mi][2], al[mi][3], Al + offA[mi][ks]);
            }
            ldm_x4(bh[0], bh[1], bh[2], bh[3], Bh + offB[ks]);
            ldm_x4(bl[0], bl[1], bl[2], bl[3], Bl + offB[ks]);
            #pragma unroll
            for (int mi = 0; mi < 2; mi++){
                #pragma unroll
                for (int na = 0; na < 2; na++){
                    mma_bf16(acc[mi][na], ah[mi], bh[na], bh[na + 2]);
                    mma_bf16(acc[mi][na], ah[mi], bl[na], bl[na + 2]);
                    mma_bf16(acc[mi][na], al[mi], bh[na], bh[na + 2]);
                }
            }
        }
        __syncthreads();
    }

    #pragma unroll
    for (int mi = 0; mi < 2; mi++){
        #pragma unroll
        for (int na = 0; na < 2; na++){
            int r  = row0 + wm*32 + mi*16 + (l >> 2);
            int cc = h*32 + wn*16 + na*8 + (l & 3)*2;
            #pragma unroll
            for (int half = 0; half < 2; half++){
                float x0 = acc[mi][na][half*2 + 0];
                float x1 = acc[mi][na][half*2 + 1];
                uint32_t h01 = cvt2(x0, x1);
                float fa = __uint_as_float(h01 << 16);
                float fb = __uint_as_float(h01 & 0xffff0000u);
                uint32_t l01 = cvt2(x0 - fa, x1 - fb);
                size_t idx = (size_t)(r + half*8)*Dz + cc;
                *(uint32_t*)(g_Fh + idx) = h01;
                *(uint32_t*)(g_Fl + idx) = l01;
            }
        }
    }
}

// ---------------- K3b: out1 = F (8192x256) @ WO^T (256x256) ----------------
// Same geometry as f_gemm: BM=128, BN=32, warp 32x16, occ 3, stage 20KB.
#define STGB 20480
#define SMEM_G3 (2*STGB)

__global__ __launch_bounds__(256, 3)
void out_gemm_kernel(float* __restrict__ out){
    extern __shared__ char smem3[];
    uint32_t sb = smem_u32(smem3);
    int t = threadIdx.x;
    int wid = t >> 5, l = t & 31;
    int wm = wid & 3, wn = wid >> 2;
    int row0 = blockIdx.x * 128;
    int col0 = blockIdx.y * 32;

    uint32_t dsw[5];
    const char* srcp[5];
    {
        const char* gAh = (const char*)g_Fh  + (size_t)row0*512;
        const char* gAl = (const char*)g_Fl  + (size_t)row0*512;
        const char* gBh = (const char*)g_WOh + (size_t)col0*512;
        const char* gBl = (const char*)g_WOl + (size_t)col0*512;
        #pragma unroll
        for (int i = 0; i < 5; i++){
            int q = t + 256*i;
            const char* base; uint32_t rb; int r;
            if      (q < 512)  { base = gAh; rb = 0;     r = q; }
            else if (q < 1024) { base = gAl; rb = 8192;  r = q - 512; }
            else if (q < 1152) { base = gBh; rb = 16384; r = q - 1024; }
            else               { base = gBl; rb = 18432; r = q - 1152; }
            int row = r >> 2, jj = r & 3;
            int line = row >> 1;
            dsw[i]  = rb + (uint32_t)(line*128 + ((((row & 1)*4 + jj) ^ (line & 7))*16));
            srcp[i] = base + (size_t)row*512 + (size_t)jj*16;
        }
    }

    uint32_t offA[2][2], offB[2];
    {
        int lr8 = ((l >> 3) & 1)*8 + (l & 7);
        int jj = l >> 4;
        #pragma unroll
        for (int mi = 0; mi < 2; mi++){
            int row = wm*32 + mi*16 + lr8;
            int line = row >> 1;
            #pragma unroll
            for (int ks = 0; ks < 2; ks++)
                offA[mi][ks] = (uint32_t)(line*128 + ((((row & 1)*4 + 2*ks + jj) ^ (line & 7))*16));
        }
        {
            int row = wn*16 + lr8;
            int line = row >> 1;
            #pragma unroll
            for (int ks = 0; ks < 2; ks++)
                offB[ks] = (uint32_t)(line*128 + ((((row & 1)*4 + 2*ks + jj) ^ (line & 7))*16));
        }
    }

    float acc[2][2][4];
    #pragma unroll
    for (int mi = 0; mi < 2; mi++)
        #pragma unroll
        for (int na = 0; na < 2; na++)
            #pragma unroll
            for (int i = 0; i < 4; i++) acc[mi][na][i] = 0.f;

    #pragma unroll
    for (int i = 0; i < 5; i++)
        cpasync16(sb + dsw[i], srcp[i]);
    CP_COMMIT();

    for (int c = 0; c < 8; c++){
        if (c + 1 < 8){
            uint32_t stg = sb + (uint32_t)((c + 1) & 1)*STGB;
            #pragma unroll
            for (int i = 0; i < 5; i++)
                cpasync16(stg + dsw[i], srcp[i] + (size_t)(c + 1)*64);
            CP_COMMIT();
            CP_WAIT(1);
        } else {
            CP_WAIT(0);
        }
        __syncthreads();

        uint32_t base = sb + (uint32_t)(c & 1)*STGB;
        uint32_t Ah = base, Al = base + 8192, Bh = base + 16384, Bl = base + 18432;
        #pragma unroll
        for (int ks = 0; ks < 2; ks++){
            uint32_t ah[2][4], al[2][4], bh[4], bl[4];
            #pragma unroll
            for (int mi = 0; mi < 2; mi++){
                ldm_x4(ah[mi][0], ah[mi][1], ah[mi][2], ah[mi][3], Ah + offA[mi][ks]);
                ldm_x4(al[mi][0], al[mi][1], al[mi][2], al[mi][3], Al + offA[mi][ks]);
            }
            ldm_x4(bh[0], bh[1], bh[2], bh[3], Bh + offB[ks]);
            ldm_x4(bl[0], bl[1], bl[2], bl[3], Bl + offB[ks]);
            #pragma unroll
            for (int mi = 0; mi < 2; mi++){
                #pragma unroll
                for (int na = 0; na < 2; na++){
                    mma_bf16(acc[mi][na], ah[mi], bh[na], bh[na + 2]);
                    mma_bf16(acc[mi][na], ah[mi], bl[na], bl[na + 2]);
                    mma_bf16(acc[mi][na], al[mi], bh[na], bh[na + 2]);
                }
            }
        }
        __syncthreads();
    }

    #pragma unroll
    for (int mi = 0; mi < 2; mi++){
        #pragma unroll
        for (int na = 0; na < 2; na++){
            int r  = row0 + wm*32 + mi*16 + (l >> 2);
            int cc = col0 + wn*16 + na*8 + (l & 3)*2;
            *(float2*)(out + (size_t)r*Dz + cc)       = make_float2(acc[mi][na][0], acc[mi][na][1]);
            *(float2*)(out + (size_t)(r + 8)*Dz + cc) = make_float2(acc[mi][na][2], acc[mi][na][3]);
        }
    }
}

// ---------------- launch ----------------------------------------------------
extern "C" void kernel_launch(void* const* d_in, const int* in_sizes, int n_in,
                              void* d_out, int out_size){
    const float* inter   = (const float*)d_in[0];
    const int*   lengths = (const int*)  d_in[1];
    const float* W       = (const float*)d_in[2];
    const float* cur_a   = (const float*)d_in[3];
    const float* nb_a    = (const float*)d_in[4];
    const float* W_out   = (const float*)d_in[5];
    float* out = (float*)d_out;

    cudaFuncSetAttribute(attn_kernel, cudaFuncAttributeMaxDynamicSharedMemorySize, SMEM_ATTN);
    cudaFuncSetAttribute(f_gemm_kernel, cudaFuncAttributeMaxDynamicSharedMemorySize, SMEM_FA);
    cudaFuncSetAttribute(out_gemm_kernel, cudaFuncAttributeMaxDynamicSharedMemorySize, SMEM_G3);

    prep_wv_kernel<<<16, 256>>>(W, cur_a, nb_a);        // launch 1
    prep_frag_kernel<<<1, 512>>>();                     // launch 2
    prep_split_kernel<<<128, 512>>>(W, W_out);          // launch 3
    attn_kernel<<<Bz, 256, SMEM_ATTN>>>(inter, lengths, out);   // launch 4 (ncu target)
    dim3 ga(Bz/128, Hz);
    f_gemm_kernel<<<ga, 256, SMEM_FA>>>();              // launch 5
    dim3 g3(Bz/128, Dz/32);
    out_gemm_kernel<<<g3, 256, SMEM_G3>>>(out);         // launch 6
}

// round 16
// speedup vs baseline: 1.0239x; 1.0239x over previous
#include <cuda_runtime.h>
#include <cuda_bf16.h>
#include <cstdint>
#include <cstddef>

#define Bz 8192
#define Nz 64
#define Dz 256
#define Hz 8
#define HHz 32
#define KTOT (Hz*Dz) /* 2048 */

// ---------------- scratch (static device globals; no allocations) ----------
__device__ float g_wv[16*Dz];                       // combined score vectors f32
__device__ uint4 g_wfH[512];                        // score B-fragments hi [wn][kk2][lane]
__device__ uint4 g_wfL[512];                        // score B-fragments lo
__device__ __nv_bfloat16 g_WTh[Dz*Dz];              // W   split hi [r][d] (r=h*32+j)
__device__ __nv_bfloat16 g_WTl[Dz*Dz];
__device__ __nv_bfloat16 g_WOh[Dz*Dz];              // W_out split hi [e][k]
__device__ __nv_bfloat16 g_WOl[Dz*Dz];
__device__ __nv_bfloat16 g_Gh[(size_t)Bz*KTOT];     // 32MB G hi [b][k]
__device__ __nv_bfloat16 g_Gl[(size_t)Bz*KTOT];     // 32MB G lo [b][k]
__device__ __nv_bfloat16 g_Fh[(size_t)Bz*Dz];       // 4MB  F hi [b][k'] (k'=h*32+j)
__device__ __nv_bfloat16 g_Fl[(size_t)Bz*Dz];

// ---------------- helpers ---------------------------------------------------
__device__ __forceinline__ uint32_t smem_u32(const void* p){
    uint32_t a;
    asm("{ .reg .u64 t; cvta.to.shared.u64 t, %1; cvt.u32.u64 %0, t; }" : "=r"(a) : "l"(p));
    return a;
}
__device__ __forceinline__ void ldm_x4(uint32_t &r0, uint32_t &r1, uint32_t &r2,
                                       uint32_t &r3, uint32_t addr){
    asm volatile("ldmatrix.sync.aligned.m8n8.x4.shared.b16 {%0,%1,%2,%3}, [%4];"
                 : "=r"(r0), "=r"(r1), "=r"(r2), "=r"(r3) : "r"(addr));
}
__device__ __forceinline__ void ldm_x4_t(uint32_t &r0, uint32_t &r1, uint32_t &r2,
                                         uint32_t &r3, uint32_t addr){
    asm volatile("ldmatrix.sync.aligned.m8n8.x4.trans.shared.b16 {%0,%1,%2,%3}, [%4];"
                 : "=r"(r0), "=r"(r1), "=r"(r2), "=r"(r3) : "r"(addr));
}
__device__ __forceinline__ void mma_bf16(float* c, const uint32_t* a,
                                         uint32_t b0, uint32_t b1){
    asm volatile(
        "mma.sync.aligned.m16n8k16.row.col.f32.bf16.bf16.f32 "
        "{%0,%1,%2,%3}, {%4,%5,%6,%7}, {%8,%9}, {%0,%1,%2,%3};"
        : "+f"(c[0]), "+f"(c[1]), "+f"(c[2]), "+f"(c[3])
        : "r"(a[0]), "r"(a[1]), "r"(a[2]), "r"(a[3]), "r"(b0), "r"(b1));
}
__device__ __forceinline__ void cpasync16(uint32_t dst, const void* src){
    asm volatile("cp.async.cg.shared.global [%0], [%1], 16;" :: "r"(dst), "l"(src) : "memory");
}
#define CP_COMMIT() asm volatile("cp.async.commit_group;" ::: "memory")
#define CP_WAIT(n)  asm volatile("cp.async.wait_group %0;" :: "n"(n) : "memory")

__device__ __forceinline__ uint32_t bf16pack(float a, float b){
    unsigned short u0 = __bfloat16_as_ushort(__float2bfloat16(a));
    unsigned short u1 = __bfloat16_as_ushort(__float2bfloat16(b));
    return (uint32_t)u0 | ((uint32_t)u1 << 16);
}
// pack two f32 -> bf16x2 in ONE cvt (first arg -> LOWER half). rn rounding.
__device__ __forceinline__ uint32_t cvt2(float lo, float hi){
    uint32_t r;
    asm("cvt.rn.bf16x2.f32 %0, %2, %1;" : "=r"(r) : "f"(lo), "f"(hi));
    return r;
}

// ---------------- K1a: wv[j][d] (parallel over 16 blocks) ------------------
__global__ __launch_bounds__(256)
void prep_wv_kernel(const float* __restrict__ W,
                    const float* __restrict__ cur_a,
                    const float* __restrict__ nb_a){
    int j = blockIdx.x;              // 0..15
    int d = threadIdx.x;
    int h = j & 7;
    const float* av = (j < 8) ? (nb_a + h*HHz) : (cur_a + h*HHz);
    float s = 0.f;
    #pragma unroll
    for (int k = 0; k < HHz; k++)
        s += av[k] * W[(h*HHz + k)*Dz + d];
    g_wv[j*Dz + d] = s;
}

// ---------------- K1b: wv -> mma B-fragment layout -------------------------
__global__ __launch_bounds__(512)
void prep_frag_kernel(){
    int t = threadIdx.x;
    int wn = t >> 8, kk2 = (t >> 5) & 7, l = t & 31;
    int j = wn*8 + (l >> 2);
    int k0 = (l & 3)*2;
    const float* row = g_wv + j*Dz + kk2*32;
    uint32_t hx[4], lx[4];
    #pragma unroll
    for (int s = 0; s < 2; s++){
        #pragma unroll
        for (int half = 0; half < 2; half++){
            float a = row[s*16 + half*8 + k0];
            float b = row[s*16 + half*8 + k0 + 1];
            float ah = __bfloat162float(__float2bfloat16(a));
            float bh = __bfloat162float(__float2bfloat16(b));
            hx[s*2 + half] = bf16pack(a, b);
            lx[s*2 + half] = bf16pack(a - ah, b - bh);
        }
    }
    g_wfH[t] = make_uint4(hx[0], hx[1], hx[2], hx[3]);
    g_wfL[t] = make_uint4(lx[0], lx[1], lx[2], lx[3]);
}

// ---------------- K1c: merged elementwise bf16 hi/lo splits ----------------
__global__ __launch_bounds__(512)
void prep_split_kernel(const float* __restrict__ W,
                       const float* __restrict__ W_out){
    int idx = blockIdx.x*512 + threadIdx.x;     // 0..65535
    float w = W[idx];
    __nv_bfloat16 hb = __float2bfloat16(w);
    g_WTh[idx] = hb;
    g_WTl[idx] = __float2bfloat16(w - __bfloat162float(hb));
    float wo = W_out[idx];
    __nv_bfloat16 ho = __float2bfloat16(wo);
    g_WOh[idx] = ho;
    g_WOl[idx] = __float2bfloat16(wo - __bfloat162float(ho));
}

// ---------------- K2: tensor-core fused attention --------------------------
// smem byte offsets (74.0 KB total -> 3 blocks/SM)
#define O_XH 0                  /* 32768 */
#define O_XL 32768              /* 32768 */
#define O_SS 65536              /* f32 [64][17] = 4352; later reused as G staging (8448B) */
#define O_AH 69888              /* 2048 */
#define O_AL 71936              /* 2048 */
#define SMEM_ATTN 73984

__global__ __launch_bounds__(256, 3)
void attn_kernel(const float* __restrict__ inter,
                 const int*   __restrict__ lengths,
                 float*       __restrict__ out){
    extern __shared__ char smem[];
    uint32_t sb = smem_u32(smem);
    float* sS = (float*)(smem + O_SS);

    int b = blockIdx.x;
    int t = threadIdx.x;
    int wid = t >> 5, l = t & 31;
    int l7 = l & 7;
    int lr8 = ((l >> 3) & 1)*8 + l7;
    int jj4 = (l >> 4) & 1;

    // ---- load X with 8-deep register prefetch, convert, store ----
    {
        const float4* src = (const float4*)(inter + (size_t)b*Nz*Dz);
        float4 buf[8];
        #pragma unroll
        for (int i = 0; i < 8; i++) buf[i] = src[t + 256*i];

        #pragma unroll
        for (int i = 0; i < 16; i++){
            float4 v = buf[i & 7];
            if (i < 8) buf[i & 7] = src[t + 256*(i + 8)];
            int g  = t + 256*i;
            int n  = g >> 6, c4 = g & 63;
            uint32_t off = (uint32_t)(n*512 + (((c4 >> 1) ^ (n & 7)) << 4) + (c4 & 1)*8);
            uint32_t h01 = cvt2(v.x, v.y);
            uint32_t h23 = cvt2(v.z, v.w);
            float fa = __uint_as_float(h01 << 16);
            float fb = __uint_as_float(h01 & 0xffff0000u);
            float fc = __uint_as_float(h23 << 16);
            float fd = __uint_as_float(h23 & 0xffff0000u);
            uint32_t l01 = cvt2(v.x - fa, v.y - fb);
            uint32_t l23 = cvt2(v.z - fc, v.w - fd);
            *(uint2*)(smem + O_XH + off) = make_uint2(h01, h23);
            *(uint2*)(smem + O_XL + off) = make_uint2(l01, l23);
            if (i == 0 && n == 0)
                *(float4*)(out + (size_t)Bz*Dz + (size_t)b*Dz + c4*4) = v;
        }
    }
    __syncthreads();

    // ---- score phase: S(64x16) = X . W^T; 4 warps, each 16 rows x ALL 16
    // cols (X smem read ONCE; B-frag global traffic unchanged) --------------
    if (wid < 4){
        int wm = wid;
        uint32_t aH = sb + O_XH + (uint32_t)((wm*16 + lr8)*512);
        uint32_t aL = sb + O_XL + (uint32_t)((wm*16 + lr8)*512);
        const uint4* pH = g_wfH + l;
        const uint4* pL = g_wfL + l;

        float c0[4] = {0.f, 0.f, 0.f, 0.f};   // n cols 0-7
        float c1[4] = {0.f, 0.f, 0.f, 0.f};   // n cols 8-15
        #pragma unroll
        for (int kk2 = 0; kk2 < 8; kk2++){
            uint4 bh0 = pH[kk2*32];
            uint4 bl0 = pL[kk2*32];
            uint4 bh1 = pH[256 + kk2*32];
            uint4 bl1 = pL[256 + kk2*32];
            #pragma unroll
            for (int s = 0; s < 2; s++){
                int kk = kk2*2 + s;
                uint32_t ao = (((uint32_t)(kk*2 + jj4) ^ l7) << 4);
                uint32_t ah[4], al[4];
                ldm_x4(ah[0], ah[1], ah[2], ah[3], aH + ao);
                ldm_x4(al[0], al[1], al[2], al[3], aL + ao);
                {
                    uint32_t b0h = s ? bh0.z : bh0.x, b1h = s ? bh0.w : bh0.y;
                    uint32_t b0l = s ? bl0.z : bl0.x, b1l = s ? bl0.w : bl0.y;
                    mma_bf16(c0, ah, b0h, b1h);
                    mma_bf16(c0, ah, b0l, b1l);
                    mma_bf16(c0, al, b0h, b1h);
                }
                {
                    uint32_t b0h = s ? bh1.z : bh1.x, b1h = s ? bh1.w : bh1.y;
                    uint32_t b0l = s ? bl1.z : bl1.x, b1l = s ? bl1.w : bl1.y;
                    mma_bf16(c1, ah, b0h, b1h);
                    mma_bf16(c1, ah, b0l, b1l);
                    mma_bf16(c1, al, b0h, b1h);
                }
            }
        }
        int r0 = wm*16 + (l >> 2);
        int jc = (l & 3)*2;
        sS[r0*17 + jc]               = c0[0];
        sS[r0*17 + jc + 1]           = c0[1];
        sS[(r0 + 8)*17 + jc]         = c0[2];
        sS[(r0 + 8)*17 + jc + 1]     = c0[3];
        sS[r0*17 + 8 + jc]           = c1[0];
        sS[r0*17 + 8 + jc + 1]       = c1[1];
        sS[(r0 + 8)*17 + 8 + jc]     = c1[2];
        sS[(r0 + 8)*17 + 8 + jc + 1] = c1[3];
    }
    __syncthreads();

    // ---- softmax per head (warp w = head h), write attn bf16 hi/lo ----
    {
        ((uint32_t*)(smem + O_AH))[256 + t] = 0u;
        ((uint32_t*)(smem + O_AL))[256 + t] = 0u;

        int h = wid;
        float cur = sS[8 + h];
        int len = lengths[b]; if (len < 1) len = 1;

        float v0 = cur + sS[l*17 + h];
        float v1 = cur + sS[(l + 32)*17 + h];
        v0 = v0 > 0.f ? v0 : 0.01f*v0;
        v1 = v1 > 0.f ? v1 : 0.01f*v1;
        bool m0 = (l < len), m1 = ((l + 32) < len);
        float y0 = m0 ? v0 : -3.0e38f;
        float y1 = m1 ? v1 : -3.0e38f;
        float mx = fmaxf(y0, y1);
        #pragma unroll
        for (int off = 16; off > 0; off >>= 1)
            mx = fmaxf(mx, __shfl_xor_sync(0xffffffffu, mx, off));
        float e0 = m0 ? __expf(v0 - mx) : 0.f;
        float e1 = m1 ? __expf(v1 - mx) : 0.f;
        float s = e0 + e1;
        #pragma unroll
        for (int off = 16; off > 0; off >>= 1)
            s += __shfl_xor_sync(0xffffffffu, s, off);
        float inv = 1.f / s;
        float a0 = e0 * inv, a1 = e1 * inv;

        int hs = h & 7;
        #pragma unroll
        for (int q = 0; q < 2; q++){
            int n = l + 32*q;
            float a = q ? a1 : a0;
            __nv_bfloat16 hb = __float2bfloat16(a);
            float lo = a - __bfloat162float(hb);
            uint32_t off = (uint32_t)(h*128 + (((n >> 3) ^ hs) << 4) + (n & 7)*2);
            *(__nv_bfloat16*)(smem + O_AH + off) = hb;
            *(__nv_bfloat16*)(smem + O_AL + off) = __float2bfloat16(lo);
        }
    }
    __syncthreads();

    // ---- G phase: G(16x256) = attn^T(16x64) . X(64x256), warp = 32 d ----
    float g[4][4];
    {
        #pragma unroll
        for (int i = 0; i < 4; i++)
            #pragma unroll
            for (int j = 0; j < 4; j++) g[i][j] = 0.f;

        uint32_t aHb = sb + O_AH + (uint32_t)(lr8*128);
        uint32_t aLb = sb + O_AL + (uint32_t)(lr8*128);

        #pragma unroll
        for (int ks = 0; ks < 4; ks++){
            uint32_t ao = (((uint32_t)(ks*2 + jj4) ^ l7) << 4);
            uint32_t ah[4], al[4];
            ldm_x4(ah[0], ah[1], ah[2], ah[3], aHb + ao);
            ldm_x4(al[0], al[1], al[2], al[3], aLb + ao);

            uint32_t rowb = (uint32_t)((ks*16 + lr8)*512);
            #pragma unroll
            for (int pair = 0; pair < 2; pair++){
                uint32_t ch = (uint32_t)(wid*4 + pair*2 + jj4);
                uint32_t xo = rowb + ((ch ^ l7) << 4);
                uint32_t xh[4], xl[4];
                ldm_x4_t(xh[0], xh[1], xh[2], xh[3], sb + O_XH + xo);
                ldm_x4_t(xl[0], xl[1], xl[2], xl[3], sb + O_XL + xo);
                mma_bf16(g[pair*2 + 0], ah, xh[0], xh[1]);
                mma_bf16(g[pair*2 + 0], ah, xl[0], xl[1]);
                mma_bf16(g[pair*2 + 0], al, xh[0], xh[1]);
                mma_bf16(g[pair*2 + 1], ah, xh[2], xh[3]);
                mma_bf16(g[pair*2 + 1], ah, xl[2], xl[3]);
                mma_bf16(g[pair*2 + 1], al, xh[2], xh[3]);
            }
        }
    }
    __syncthreads();   // all G-phase smem reads done; staging may overwrite

    // ---- stage G fragments (conflict-free), then coalesced writeout ----
    {
        uint32_t* sG32 = (uint32_t*)(smem + O_SS);   // hi [8][132], lo at +1056
        int h = l >> 2;
        #pragma unroll
        for (int i = 0; i < 4; i++){
            uint32_t h01 = cvt2(g[i][0], g[i][1]);
            float fa = __uint_as_float(h01 << 16);
            float fb = __uint_as_float(h01 & 0xffff0000u);
            uint32_t l01 = cvt2(g[i][0] - fa, g[i][1] - fb);
            int idx = h*132 + wid*16 + i*4 + (l & 3);
            sG32[idx]        = h01;
            sG32[1056 + idx] = l01;
        }
    }
    __syncthreads();
    {
        int row = t >> 5, c = t & 31;
        uint32_t* sG32 = (uint32_t*)(smem + O_SS);
        uint4 vh = *(uint4*)(sG32 + row*132 + c*4);
        uint4 vl = *(uint4*)(sG32 + 1056 + row*132 + c*4);
        uint32_t* Gh = (uint32_t*)(g_Gh + (size_t)b*KTOT);
        uint32_t* Gl = (uint32_t*)(g_Gl + (size_t)b*KTOT);
        *(uint4*)(Gh + row*128 + c*4) = vh;
        *(uint4*)(Gl + row*128 + c*4) = vl;
    }
}

// ---------------- K3a: F[b, h*32+j] = sum_d G[b,(h,d)] W[h*32+j, d] --------
#define STGA 20480
#define SMEM_FA (2*STGA)

__global__ __launch_bounds__(256, 3)
void f_gemm_kernel(){
    extern __shared__ char smemA[];
    uint32_t sb = smem_u32(smemA);
    int t = threadIdx.x;
    int wid = t >> 5, l = t & 31;
    int wm = wid & 3, wn = wid >> 2;
    int row0 = blockIdx.x * 128;
    int h    = blockIdx.y;

    uint32_t dsw[5];
    const char* srcp[5];
    {
        const char* gAh = (const char*)g_Gh  + (size_t)row0*4096 + (size_t)h*512;
        const char* gAl = (const char*)g_Gl  + (size_t)row0*4096 + (size_t)h*512;
        const char* gBh = (const char*)g_WTh + (size_t)h*32*512;
        const char* gBl = (const char*)g_WTl + (size_t)h*32*512;
        #pragma unroll
        for (int i = 0; i < 5; i++){
            int q = t + 256*i;
            const char* base; uint32_t rb; int r; size_t rstride;
            if      (q < 512)  { base = gAh; rb = 0;     r = q;        rstride = 4096; }
            else if (q < 1024) { base = gAl; rb = 8192;  r = q - 512;  rstride = 4096; }
            else if (q < 1152) { base = gBh; rb = 16384; r = q - 1024; rstride = 512; }
            else               { base = gBl; rb = 18432; r = q - 1152; rstride = 512; }
            int row = r >> 2, jj = r & 3;
            int line = row >> 1;
            dsw[i]  = rb + (uint32_t)(line*128 + ((((row & 1)*4 + jj) ^ (line & 7))*16));
            srcp[i] = base + (size_t)row*rstride + (size_t)jj*16;
        }
    }

    uint32_t offA[2][2], offB[2];
    {
        int lr8 = ((l >> 3) & 1)*8 + (l & 7);
        int jj = l >> 4;
        #pragma unroll
        for (int mi = 0; mi < 2; mi++){
            int row = wm*32 + mi*16 + lr8;
            int line = row >> 1;
            #pragma unroll
            for (int ks = 0; ks < 2; ks++)
                offA[mi][ks] = (uint32_t)(line*128 + ((((row & 1)*4 + 2*ks + jj) ^ (line & 7))*16));
        }
        {
            int row = wn*16 + lr8;
            int line = row >> 1;
            #pragma unroll
            for (int ks = 0; ks < 2; ks++)
                offB[ks] = (uint32_t)(line*128 + ((((row & 1)*4 + 2*ks + jj) ^ (line & 7))*16));
        }
    }

    float acc[2][2][4];
    #pragma unroll
    for (int mi = 0; mi < 2; mi++)
        #pragma unroll
        for (int na = 0; na < 2; na++)
            #pragma unroll
            for (int i = 0; i < 4; i++) acc[mi][na][i] = 0.f;

    #pragma unroll
    for (int i = 0; i < 5; i++)
        cpasync16(sb + dsw[i], srcp[i]);
    CP_COMMIT();

    for (int c = 0; c < 8; c++){
        if (c + 1 < 8){
            uint32_t stg = sb + (uint32_t)((c + 1) & 1)*STGA;
            #pragma unroll
            for (int i = 0; i < 5; i++)
                cpasync16(stg + dsw[i], srcp[i] + (size_t)(c + 1)*64);
            CP_COMMIT();
            CP_WAIT(1);
        } else {
            CP_WAIT(0);
        }
        __syncthreads();

        uint32_t base = sb + (uint32_t)(c & 1)*STGA;
        uint32_t Ah = base, Al = base + 8192, Bh = base + 16384, Bl = base + 18432;
        #pragma unroll
        for (int ks = 0; ks < 2; ks++){
            uint32_t ah[2][4], al[2][4], bh[4], bl[4];
            #pragma unroll
            for (int mi = 0; mi < 2; mi++){
                ldm_x4(ah[mi][0], ah[mi][1], ah[mi][2], ah[mi][3], Ah + offA[mi][ks]);
                ldm_x4(al[mi][0], al[mi][1], al[mi][2], al[mi][3], Al + offA[mi][ks]);
            }
            ldm_x4(bh[0], bh[1], bh[2], bh[3], Bh + offB[ks]);
            ldm_x4(bl[0], bl[1], bl[2], bl[3], Bl + offB[ks]);
            #pragma unroll
            for (int mi = 0; mi < 2; mi++){
                #pragma unroll
                for (int na = 0; na < 2; na++){
                    mma_bf16(acc[mi][na], ah[mi], bh[na], bh[na + 2]);
                    mma_bf16(acc[mi][na], ah[mi], bl[na], bl[na + 2]);
                    mma_bf16(acc[mi][na], al[mi], bh[na], bh[na + 2]);
                }
            }
        }
        __syncthreads();
    }

    #pragma unroll
    for (int mi = 0; mi < 2; mi++){
        #pragma unroll
        for (int na = 0; na < 2; na++){
            int r  = row0 + wm*32 + mi*16 + (l >> 2);
            int cc = h*32 + wn*16 + na*8 + (l & 3)*2;
            #pragma unroll
            for (int half = 0; half < 2; half++){
                float x0 = acc[mi][na][half*2 + 0];
                float x1 = acc[mi][na][half*2 + 1];
                uint32_t h01 = cvt2(x0, x1);
                float fa = __uint_as_float(h01 << 16);
                float fb = __uint_as_float(h01 & 0xffff0000u);
                uint32_t l01 = cvt2(x0 - fa, x1 - fb);
                size_t idx = (size_t)(r + half*8)*Dz + cc;
                *(uint32_t*)(g_Fh + idx) = h01;
                *(uint32_t*)(g_Fl + idx) = l01;
            }
        }
    }
}

// ---------------- K3b: out1 = F (8192x256) @ WO^T (256x256) ----------------
#define STGB 20480
#define SMEM_G3 (2*STGB)

__global__ __launch_bounds__(256, 3)
void out_gemm_kernel(float* __restrict__ out){
    extern __shared__ char smem3[];
    uint32_t sb = smem_u32(smem3);
    int t = threadIdx.x;
    int wid = t >> 5, l = t & 31;
    int wm = wid & 3, wn = wid >> 2;
    int row0 = blockIdx.x * 128;
    int col0 = blockIdx.y * 32;

    uint32_t dsw[5];
    const char* srcp[5];
    {
        const char* gAh = (const char*)g_Fh  + (size_t)row0*512;
        const char* gAl = (const char*)g_Fl  + (size_t)row0*512;
        const char* gBh = (const char*)g_WOh + (size_t)col0*512;
        const char* gBl = (const char*)g_WOl + (size_t)col0*512;
        #pragma unroll
        for (int i = 0; i < 5; i++){
            int q = t + 256*i;
            const char* base; uint32_t rb; int r;
            if      (q < 512)  { base = gAh; rb = 0;     r = q; }
            else if (q < 1024) { base = gAl; rb = 8192;  r = q - 512; }
            else if (q < 1152) { base = gBh; rb = 16384; r = q - 1024; }
            else               { base = gBl; rb = 18432; r = q - 1152; }
            int row = r >> 2, jj = r & 3;
            int line = row >> 1;
            dsw[i]  = rb + (uint32_t)(line*128 + ((((row & 1)*4 + jj) ^ (line & 7))*16));
            srcp[i] = base + (size_t)row*512 + (size_t)jj*16;
        }
    }

    uint32_t offA[2][2], offB[2];
    {
        int lr8 = ((l >> 3) & 1)*8 + (l & 7);
        int jj = l >> 4;
        #pragma unroll
        for (int mi = 0; mi < 2; mi++){
            int row = wm*32 + mi*16 + lr8;
            int line = row >> 1;
            #pragma unroll
            for (int ks = 0; ks < 2; ks++)
                offA[mi][ks] = (uint32_t)(line*128 + ((((row & 1)*4 + 2*ks + jj) ^ (line & 7))*16));
        }
        {
            int row = wn*16 + lr8;
            int line = row >> 1;
            #pragma unroll
            for (int ks = 0; ks < 2; ks++)
                offB[ks] = (uint32_t)(line*128 + ((((row & 1)*4 + 2*ks + jj) ^ (line & 7))*16));
        }
    }

    float acc[2][2][4];
    #pragma unroll
    for (int mi = 0; mi < 2; mi++)
        #pragma unroll
        for (int na = 0; na < 2; na++)
            #pragma unroll
            for (int i = 0; i < 4; i++) acc[mi][na][i] = 0.f;

    #pragma unroll
    for (int i = 0; i < 5; i++)
        cpasync16(sb + dsw[i], srcp[i]);
    CP_COMMIT();

    for (int c = 0; c < 8; c++){
        if (c + 1 < 8){
            uint32_t stg = sb + (uint32_t)((c + 1) & 1)*STGB;
            #pragma unroll
            for (int i = 0; i < 5; i++)
                cpasync16(stg + dsw[i], srcp[i] + (size_t)(c + 1)*64);
            CP_COMMIT();
            CP_WAIT(1);
        } else {
            CP_WAIT(0);
        }
        __syncthreads();

        uint32_t base = sb + (uint32_t)(c & 1)*STGB;
        uint32_t Ah = base, Al = base + 8192, Bh = base + 16384, Bl = base + 18432;
        #pragma unroll
        for (int ks = 0; ks < 2; ks++){
            uint32_t ah[2][4], al[2][4], bh[4], bl[4];
            #pragma unroll
            for (int mi = 0; mi < 2; mi++){
                ldm_x4(ah[mi][0], ah[mi][1], ah[mi][2], ah[mi][3], Ah + offA[mi][ks]);
                ldm_x4(al[mi][0], al[mi][1], al[mi][2], al[mi][3], Al + offA[mi][ks]);
            }
            ldm_x4(bh[0], bh[1], bh[2], bh[3], Bh + offB[ks]);
            ldm_x4(bl[0], bl[1], bl[2], bl[3], Bl + offB[ks]);
            #pragma unroll
            for (int mi = 0; mi < 2; mi++){
                #pragma unroll
                for (int na = 0; na < 2; na++){
                    mma_bf16(acc[mi][na], ah[mi], bh[na], bh[na + 2]);
                    mma_bf16(acc[mi][na], ah[mi], bl[na], bl[na + 2]);
                    mma_bf16(acc[mi][na], al[mi], bh[na], bh[na + 2]);
                }
            }
        }
        __syncthreads();
    }

    #pragma unroll
    for (int mi = 0; mi < 2; mi++){
        #pragma unroll
        for (int na = 0; na < 2; na++){
            int r  = row0 + wm*32 + mi*16 + (l >> 2);
            int cc = col0 + wn*16 + na*8 + (l & 3)*2;
            *(float2*)(out + (size_t)r*Dz + cc)       = make_float2(acc[mi][na][0], acc[mi][na][1]);
            *(float2*)(out + (size_t)(r + 8)*Dz + cc) = make_float2(acc[mi][na][2], acc[mi][na][3]);
        }
    }
}

// ---------------- launch ----------------------------------------------------
extern "C" void kernel_launch(void* const* d_in, const int* in_sizes, int n_in,
                              void* d_out, int out_size){
    const float* inter   = (const float*)d_in[0];
    const int*   lengths = (const int*)  d_in[1];
    const float* W       = (const float*)d_in[2];
    const float* cur_a   = (const float*)d_in[3];
    const float* nb_a    = (const float*)d_in[4];
    const float* W_out   = (const float*)d_in[5];
    float* out = (float*)d_out;

    cudaFuncSetAttribute(attn_kernel, cudaFuncAttributeMaxDynamicSharedMemorySize, SMEM_ATTN);
    cudaFuncSetAttribute(f_gemm_kernel, cudaFuncAttributeMaxDynamicSharedMemorySize, SMEM_FA);
    cudaFuncSetAttribute(out_gemm_kernel, cudaFuncAttributeMaxDynamicSharedMemorySize, SMEM_G3);

    prep_wv_kernel<<<16, 256>>>(W, cur_a, nb_a);        // launch 1
    prep_frag_kernel<<<1, 512>>>();                     // launch 2
    prep_split_kernel<<<128, 512>>>(W, W_out);          // launch 3
    attn_kernel<<<Bz, 256, SMEM_ATTN>>>(inter, lengths, out);   // launch 4 (ncu target)
    dim3 ga(Bz/128, Hz);
    f_gemm_kernel<<<ga, 256, SMEM_FA>>>();              // launch 5
    dim3 g3(Bz/128, Dz/32);
    out_gemm_kernel<<<g3, 256, SMEM_G3>>>(out);         // launch 6
}